// round 7
// baseline (speedup 1.0000x reference)
#include <cuda_runtime.h>

#define NXC 512
#define NYC 512
#define PHW 3
#define PP 6                  // patch size
#define BB 128
#define SS 1024
#define BH 8                  // band height (rows)
#define BW 516                // padded band width (bank-spread)
#define BANDS_PER_IMG (NXC / BH)      // 64
#define NBANDS (BB * BANDS_PER_IMG)   // 8192
#define CAP 96                // max sources per band (mean ~26)

__device__ __forceinline__ float inv_alpha() { return 1.0f / (1.41421356237309515f * 0.92f); }

__device__ int    g_cnt[NBANDS];              // zero at load; render re-zeroes its own bin
__device__ float2 g_src[NBANDS * CAP];

__global__ void bin_kernel(const float* __restrict__ z) {
    int gid = blockIdx.x * blockDim.x + threadIdx.x;
    if (gid >= BB * SS) return;
    int b = gid >> 10;
    int s = gid & (SS - 1);

    float x0 = __ldg(&z[b * 2 * SS + s]);
    float y0 = __ldg(&z[b * 2 * SS + SS + s]);

    int patchx = __float2int_rn(x0) - PHW;
    int patchy = __float2int_rn(y0) - PHW;
    if (patchx < 0 || patchx >= NXC - PP || patchy < 0 || patchy >= NYC - PP) return;

    int band0 = patchx >> 3;
    int band1 = (patchx + PP - 1) >> 3;
    for (int bd = band0; bd <= band1; ++bd) {
        int bin = b * BANDS_PER_IMG + bd;
        int pos = atomicAdd(&g_cnt[bin], 1);
        if (pos < CAP) g_src[bin * CAP + pos] = make_float2(x0, y0);
    }
}

__global__ __launch_bounds__(256, 8) void render_kernel(float* __restrict__ out) {
    __shared__ float band[BH * BW];           // 16.5 KB accumulation buffer
    __shared__ int   s_px[CAP];
    __shared__ int   s_py[CAP];
    __shared__ float s_lx[CAP * PP];
    __shared__ float s_ly[CAP * PP];
    __shared__ int   s_n;

    int bin = blockIdx.x;
    int b   = bin >> 6;                               // image
    int r0  = (bin & (BANDS_PER_IMG - 1)) << 3;       // first global row of band
    int tid = threadIdx.x;
    int wid = tid >> 5;
    int lane = tid & 31;

    // issue the count load first; zeroing below hides its latency
    if (tid == 0) {
        int n = g_cnt[bin];
        s_n = (n > CAP) ? CAP : n;
        g_cnt[bin] = 0;                               // restore for next graph replay
    }

    // zero band: 1032 float4 over 256 threads
    float4* bz = (float4*)band;
    for (int i = tid; i < BH * BW / 4; i += 256)
        bz[i] = make_float4(0.f, 0.f, 0.f, 0.f);
    __syncthreads();

    int n = s_n;

    // per-source-per-axis profile setup: 2 threads per source
    if (tid < 2 * n) {
        int sid = tid >> 1;
        int ax  = tid & 1;
        float2 xy = g_src[bin * CAP + sid];
        float u0 = ax ? xy.y : xy.x;
        int pu = __float2int_rn(u0) - PHW;
        float up = u0 - (float)pu;
        const float ia = inv_alpha();

        float e[PP + 1];
#pragma unroll
        for (int k = 0; k <= PP; k++)
            e[k] = erff(((float)k - 0.5f - up) * ia);

        if (ax == 0) {
            s_px[sid] = pu;
#pragma unroll
            for (int k = 0; k < PP; k++)
                s_lx[sid * PP + k] = 500.0f * (e[k + 1] - e[k]);  // i0*0.5 folded
        } else {
            s_py[sid] = pu;
#pragma unroll
            for (int k = 0; k < PP; k++)
                s_ly[sid * PP + k] = 0.5f * (e[k + 1] - e[k]);
        }
    }
    __syncthreads();

    // accumulate: warp w takes sources w, w+8, ...; lanes cover the 36 patch pixels
    for (int s = wid; s < n; s += 8) {
        int rl = s_px[s] - r0;                // local patch-origin row, in [-5, 7]
        int py = s_py[s];
#pragma unroll
        for (int rep = 0; rep < 2; ++rep) {
            int p = lane + rep * 32;
            if (p < PP * PP) {
                int i = p / PP;
                int j = p - i * PP;
                int r = rl + i;
                if ((unsigned)r < (unsigned)BH) {
                    float v = s_lx[s * PP + i] * s_ly[s * PP + j];
                    atomicAdd(&band[r * BW + py + j], v);
                }
            }
        }
    }
    __syncthreads();

    // stream band to gmem: coalesced float4 (skip row padding)
    float4* dst = (float4*)(out + (size_t)b * NXC * NYC + (size_t)r0 * NYC);
#pragma unroll
    for (int k = 0; k < 4; ++k) {
        int f = k * 256 + tid;                // output float4 index within 8x512 band
        int row = f >> 7;
        int c4  = f & 127;
        dst[f] = *(float4*)&band[row * BW + (c4 << 2)];
    }
}

extern "C" void kernel_launch(void* const* d_in, const int* in_sizes, int n_in,
                              void* d_out, int out_size) {
    const float* z = (const float*)d_in[0];
    float* out = (float*)d_out;

    bin_kernel<<<(BB * SS + 255) / 256, 256>>>(z);
    render_kernel<<<NBANDS, 256>>>(out);
}